// round 12
// baseline (speedup 1.0000x reference)
#include <cuda_runtime.h>
#include <cuda_bf16.h>

using bf16 = __nv_bfloat16;
using bf162 = __nv_bfloat162;

#define SEQ 1024
#define NB 4
#define NH 16
#define HD 64
#define LN_EPS 1e-5f

// ---------------- scratch (device globals; no allocations allowed) ----------
__device__ bf16 g_xhi[4194304],  g_xlo[4194304];     // x split
__device__ bf16 g_chi[4194304],  g_clo[4194304];     // context split
__device__ bf16 g_wqThi[1048576], g_wqTlo[1048576];  // Wq^T  [n][k]
__device__ bf16 g_wkThi[2097152], g_wkTlo[2097152];  // Wkv^T [n][k]
__device__ float g_q[4194304];                        // x@Wq fp32
__device__ float g_kv[8388608];                       // ctx@Wkv fp32 (k|v)
__device__ bf16 g_qhi[4194304],  g_qlo[4194304];
__device__ bf16 g_kvhi[8388608], g_kvlo[8388608];
__device__ bf16 g_vThi[4194304], g_vTlo[4194304];    // v^T per batch [d][j]
__device__ float g_s[67108864];                       // raw scores [b][i][h][j]
__device__ bf16 g_whi[67108864], g_wlo[67108864];    // mixed+LN weights [b,g][i][j]

// ---------------- split fp32 -> bf16 hi/lo ----------------------------------
__global__ __launch_bounds__(256) void split_kernel(
    const float* __restrict__ in, bf16* __restrict__ hi, bf16* __restrict__ lo, int n)
{
    int i = (blockIdx.x * 256 + threadIdx.x) * 4;
    if (i >= n) return;
    float4 v = *(const float4*)(in + i);
    bf16 h0 = __float2bfloat16(v.x), h1 = __float2bfloat16(v.y);
    bf16 h2 = __float2bfloat16(v.z), h3 = __float2bfloat16(v.w);
    bf16 l0 = __float2bfloat16(v.x - __bfloat162float(h0));
    bf16 l1 = __float2bfloat16(v.y - __bfloat162float(h1));
    bf16 l2 = __float2bfloat16(v.z - __bfloat162float(h2));
    bf16 l3 = __float2bfloat16(v.w - __bfloat162float(h3));
    bf162 p;
    p.x = h0; p.y = h1; *(bf162*)(hi + i)     = p;
    p.x = h2; p.y = h3; *(bf162*)(hi + i + 2) = p;
    p.x = l0; p.y = l1; *(bf162*)(lo + i)     = p;
    p.x = l2; p.y = l3; *(bf162*)(lo + i + 2) = p;
}

// ---------------- transpose + split: out[c][r] = in[r][c] -------------------
__global__ __launch_bounds__(256) void tsplit_kernel(
    const float* __restrict__ in, long inZ, int inStride,
    bf16* __restrict__ hi, bf16* __restrict__ lo, long outZ, int outStride)
{
    __shared__ float tile[32][33];
    const float* ip = in + (long)blockIdx.z * inZ;
    int r0 = blockIdx.y * 32, c0 = blockIdx.x * 32;
    int t = threadIdx.x;
    {
        int r = t >> 3, c4 = (t & 7) * 4;
        float4 v = *(const float4*)(ip + (long)(r0 + r) * inStride + c0 + c4);
        tile[r][c4] = v.x; tile[r][c4 + 1] = v.y; tile[r][c4 + 2] = v.z; tile[r][c4 + 3] = v.w;
    }
    __syncthreads();
    int c = t >> 3, r4 = (t & 7) * 4;
    long ob = (long)blockIdx.z * outZ + (long)(c0 + c) * outStride + r0 + r4;
    float f0 = tile[r4][c], f1 = tile[r4 + 1][c], f2 = tile[r4 + 2][c], f3 = tile[r4 + 3][c];
    bf16 h0 = __float2bfloat16(f0), h1 = __float2bfloat16(f1);
    bf16 h2 = __float2bfloat16(f2), h3 = __float2bfloat16(f3);
    bf162 p;
    p.x = h0; p.y = h1; *(bf162*)(hi + ob)     = p;
    p.x = h2; p.y = h3; *(bf162*)(hi + ob + 2) = p;
    p.x = __float2bfloat16(f0 - __bfloat162float(h0));
    p.y = __float2bfloat16(f1 - __bfloat162float(h1));
    *(bf162*)(lo + ob) = p;
    p.x = __float2bfloat16(f2 - __bfloat162float(h2));
    p.y = __float2bfloat16(f3 - __bfloat162float(h3));
    *(bf162*)(lo + ob + 2) = p;
}

// ---------------- mma.sync helper -------------------------------------------
__device__ __forceinline__ void mma16816(float* d, const unsigned* a, unsigned b0, unsigned b1)
{
    asm volatile(
        "mma.sync.aligned.m16n8k16.row.col.f32.bf16.bf16.f32 "
        "{%0,%1,%2,%3}, {%4,%5,%6,%7}, {%8,%9}, {%0,%1,%2,%3};\n"
        : "+f"(d[0]), "+f"(d[1]), "+f"(d[2]), "+f"(d[3])
        : "r"(a[0]), "r"(a[1]), "r"(a[2]), "r"(a[3]), "r"(b0), "r"(b1));
}

// ---------------- split-bf16 GEMM: C[m][n] = sum_k A[m][k] * B[n][k] --------
template <int BM, int BNt, int WM, int WNt>
__global__ __launch_bounds__(256) void gemm_bf16(
    const bf16* __restrict__ Ahi, const bf16* __restrict__ Alo,
    const bf16* __restrict__ Bhi, const bf16* __restrict__ Blo,
    float* __restrict__ C, int K, int lda, int ldb, int ldc,
    int HB, long sA1, long sA2, long sB1, long sB2, long sC1, long sC2)
{
    constexpr int KS = 40;                 // smem stride (bf16 units), conflict-free
    __shared__ bf16 As[2][BM * KS];
    __shared__ bf16 Bs[2][BNt * KS];

    int z = blockIdx.z;
    long zb = z / HB, zr = z % HB;
    const bf16* Ah = Ahi + zb * sA1 + zr * sA2 + (long)(blockIdx.y * BM) * lda;
    const bf16* Al = Alo + zb * sA1 + zr * sA2 + (long)(blockIdx.y * BM) * lda;
    const bf16* Bh = Bhi + zb * sB1 + zr * sB2 + (long)(blockIdx.x * BNt) * ldb;
    const bf16* Bl = Blo + zb * sB1 + zr * sB2 + (long)(blockIdx.x * BNt) * ldb;
    float* Cp = C + zb * sC1 + zr * sC2 + (long)(blockIdx.y * BM) * ldc + blockIdx.x * BNt;

    int t = threadIdx.x, w = t >> 5, lane = t & 31;
    constexpr int MW = BM / WM;
    constexpr int MB = WM / 16, NBk = WNt / 8;
    int mw = (w % MW) * WM, nw = (w / MW) * WNt;
    int fr = lane >> 2, fc = (lane & 3) * 2;

    float acc[MB][NBk][4];
#pragma unroll
    for (int i = 0; i < MB; i++)
#pragma unroll
        for (int j = 0; j < NBk; j++)
#pragma unroll
            for (int e = 0; e < 4; e++) acc[i][j][e] = 0.f;

    for (int k0 = 0; k0 < K; k0 += 32) {
        __syncthreads();
#pragma unroll 2
        for (int i = t; i < BM * 4; i += 256) {
            int m = i >> 2, kv = (i & 3) * 8;
            *(uint4*)&As[0][m * KS + kv] = *(const uint4*)(Ah + (long)m * lda + k0 + kv);
            *(uint4*)&As[1][m * KS + kv] = *(const uint4*)(Al + (long)m * lda + k0 + kv);
        }
#pragma unroll 2
        for (int i = t; i < BNt * 4; i += 256) {
            int n = i >> 2, kv = (i & 3) * 8;
            *(uint4*)&Bs[0][n * KS + kv] = *(const uint4*)(Bh + (long)n * ldb + k0 + kv);
            *(uint4*)&Bs[1][n * KS + kv] = *(const uint4*)(Bl + (long)n * ldb + k0 + kv);
        }
        __syncthreads();
#pragma unroll
        for (int ks = 0; ks < 32; ks += 16) {
            unsigned ah[MB][4], al[MB][4];
#pragma unroll
            for (int mb = 0; mb < MB; mb++) {
                int mbase = mw + mb * 16;
                ah[mb][0] = *(unsigned*)&As[0][(mbase + fr) * KS + ks + fc];
                ah[mb][1] = *(unsigned*)&As[0][(mbase + fr + 8) * KS + ks + fc];
                ah[mb][2] = *(unsigned*)&As[0][(mbase + fr) * KS + ks + fc + 8];
                ah[mb][3] = *(unsigned*)&As[0][(mbase + fr + 8) * KS + ks + fc + 8];
                al[mb][0] = *(unsigned*)&As[1][(mbase + fr) * KS + ks + fc];
                al[mb][1] = *(unsigned*)&As[1][(mbase + fr + 8) * KS + ks + fc];
                al[mb][2] = *(unsigned*)&As[1][(mbase + fr) * KS + ks + fc + 8];
                al[mb][3] = *(unsigned*)&As[1][(mbase + fr + 8) * KS + ks + fc + 8];
            }
#pragma unroll
            for (int nb = 0; nb < NBk; nb++) {
                int nbase = nw + nb * 8 + fr;
                unsigned bh0 = *(unsigned*)&Bs[0][nbase * KS + ks + fc];
                unsigned bh1 = *(unsigned*)&Bs[0][nbase * KS + ks + fc + 8];
                unsigned bl0 = *(unsigned*)&Bs[1][nbase * KS + ks + fc];
                unsigned bl1 = *(unsigned*)&Bs[1][nbase * KS + ks + fc + 8];
#pragma unroll
                for (int mb = 0; mb < MB; mb++) {
                    mma16816(acc[mb][nb], ah[mb], bh0, bh1);  // hi*hi
                    mma16816(acc[mb][nb], ah[mb], bl0, bl1);  // hi*lo
                    mma16816(acc[mb][nb], al[mb], bh0, bh1);  // lo*hi
                }
            }
        }
    }
    // epilogue
#pragma unroll
    for (int mb = 0; mb < MB; mb++)
#pragma unroll
        for (int nb = 0; nb < NBk; nb++) {
            float* cp = Cp + (long)(mw + mb * 16 + fr) * ldc + nw + nb * 8 + fc;
            *(float2*)cp = make_float2(acc[mb][nb][0], acc[mb][nb][1]);
            *(float2*)(cp + (long)8 * ldc) = make_float2(acc[mb][nb][2], acc[mb][nb][3]);
        }
}

// ---------------- FUSED softmax + talking-heads mix + LN --------------------
// CTA = (b,i). Loads raw scores for all 16 heads into smem (16 x 1024 fp32),
// does 16 row-softmaxes in smem, then the 16x16 mix + LayerNorm per j, and
// writes w [b,g][i][j] as split bf16. One read of g_s, one write of w.
#define SSTR 1032
__global__ __launch_bounds__(256) void softmax_mixln_kernel(
    const float* __restrict__ s, const float* __restrict__ Wt,
    const float* __restrict__ gamma, const float* __restrict__ beta,
    bf16* __restrict__ whi, bf16* __restrict__ wlo)
{
    extern __shared__ float sm[];            // [16][SSTR] scores -> probs
    __shared__ float wts[16][17];
    __shared__ float gm[16], bt[16];
    int t = threadIdx.x;
    wts[t >> 4][t & 15] = Wt[t];
    if (t < 16) { gm[t] = gamma[t]; bt[t] = beta[t]; }

    long bi = blockIdx.x;                    // b*1024 + i
    const float* sp = s + bi * 16384;
    // load all 16 head-rows (float4)
#pragma unroll 4
    for (int idx = t; idx < 16 * 256; idx += 256) {
        int h = idx >> 8, j4 = idx & 255;
        float4 v = ((const float4*)(sp + h * 1024))[j4];
        *(float4*)&sm[h * SSTR + j4 * 4] = v;
    }
    __syncthreads();

    // softmax: 8 warps, 2 rows each, in smem
    int w = t >> 5, lane = t & 31;
#pragma unroll
    for (int rr = 0; rr < 2; rr++) {
        float* rp = &sm[(w * 2 + rr) * SSTR];
        float mx = -1e30f;
#pragma unroll 8
        for (int j = lane; j < 1024; j += 32) mx = fmaxf(mx, rp[j]);
#pragma unroll
        for (int o = 16; o > 0; o >>= 1) mx = fmaxf(mx, __shfl_xor_sync(0xffffffffu, mx, o));
        float sum = 0.f;
#pragma unroll 8
        for (int j = lane; j < 1024; j += 32) {
            float e = __expf(0.125f * (rp[j] - mx));
            rp[j] = e;
            sum += e;
        }
#pragma unroll
        for (int o = 16; o > 0; o >>= 1) sum += __shfl_xor_sync(0xffffffffu, sum, o);
        float inv = 1.f / sum;
#pragma unroll 8
        for (int j = lane; j < 1024; j += 32) rp[j] *= inv;
    }
    __syncthreads();

    // mix + LN, two j-pairs per thread: j0 = 2t and 512 + 2t
    long b = bi >> 10, i = bi & 1023;
#pragma unroll
    for (int pass = 0; pass < 2; pass++) {
        int j0 = pass * 512 + t * 2;
        float sv0[16], sv1[16];
#pragma unroll
        for (int h = 0; h < 16; h++) {
            float2 v = *(const float2*)&sm[h * SSTR + j0];
            sv0[h] = v.x; sv1[h] = v.y;
        }
        float m0[16], m1[16], mu0 = 0.f, mu1 = 0.f;
#pragma unroll
        for (int g = 0; g < 16; g++) {
            float a = 0.f, b2 = 0.f;
#pragma unroll
            for (int h = 0; h < 16; h++) {
                a  = fmaf(sv0[h], wts[h][g], a);
                b2 = fmaf(sv1[h], wts[h][g], b2);
            }
            m0[g] = a; m1[g] = b2; mu0 += a; mu1 += b2;
        }
        mu0 *= (1.f / 16.f); mu1 *= (1.f / 16.f);
        float va0 = 0.f, va1 = 0.f;
#pragma unroll
        for (int g = 0; g < 16; g++) {
            float d0 = m0[g] - mu0, d1 = m1[g] - mu1;
            va0 = fmaf(d0, d0, va0); va1 = fmaf(d1, d1, va1);
        }
        float iv0 = rsqrtf(va0 * (1.f / 16.f) + LN_EPS);
        float iv1 = rsqrtf(va1 * (1.f / 16.f) + LN_EPS);
#pragma unroll
        for (int g = 0; g < 16; g++) {
            float w0 = (m0[g] - mu0) * iv0 * gm[g] + bt[g];
            float w1 = (m1[g] - mu1) * iv1 * gm[g] + bt[g];
            bf16 h0 = __float2bfloat16(w0), h1 = __float2bfloat16(w1);
            bf162 ph; ph.x = h0; ph.y = h1;
            bf162 pl;
            pl.x = __float2bfloat16(w0 - __bfloat162float(h0));
            pl.y = __float2bfloat16(w1 - __bfloat162float(h1));
            long ob = ((b * 16 + g) << 20) + (i << 10) + j0;
            *(bf162*)(whi + ob) = ph;
            *(bf162*)(wlo + ob) = pl;
        }
    }
}

// ---------------- driver -----------------------------------------------------
extern "C" void kernel_launch(void* const* d_in, const int* in_sizes, int n_in,
                              void* d_out, int out_size)
{
    const float* x     = (const float*)d_in[0];
    const float* ctx   = (const float*)d_in[1];
    const float* Wq    = (const float*)d_in[2];
    const float* Wkv   = (const float*)d_in[3];
    const float* Wt    = (const float*)d_in[4];
    const float* gamma = (const float*)d_in[5];
    const float* beta  = (const float*)d_in[6];
    float* out = (float*)d_out;

    bf16 *xhi, *xlo, *chi, *clo, *wqThi, *wqTlo, *wkThi, *wkTlo;
    bf16 *qhi, *qlo, *kvhi, *kvlo, *vThi, *vTlo, *whi, *wlo;
    float *qp, *kvp, *sp;
    cudaGetSymbolAddress((void**)&xhi, g_xhi);   cudaGetSymbolAddress((void**)&xlo, g_xlo);
    cudaGetSymbolAddress((void**)&chi, g_chi);   cudaGetSymbolAddress((void**)&clo, g_clo);
    cudaGetSymbolAddress((void**)&wqThi, g_wqThi); cudaGetSymbolAddress((void**)&wqTlo, g_wqTlo);
    cudaGetSymbolAddress((void**)&wkThi, g_wkThi); cudaGetSymbolAddress((void**)&wkTlo, g_wkTlo);
    cudaGetSymbolAddress((void**)&qhi, g_qhi);   cudaGetSymbolAddress((void**)&qlo, g_qlo);
    cudaGetSymbolAddress((void**)&kvhi, g_kvhi); cudaGetSymbolAddress((void**)&kvlo, g_kvlo);
    cudaGetSymbolAddress((void**)&vThi, g_vThi); cudaGetSymbolAddress((void**)&vTlo, g_vTlo);
    cudaGetSymbolAddress((void**)&whi, g_whi);   cudaGetSymbolAddress((void**)&wlo, g_wlo);
    cudaGetSymbolAddress((void**)&qp, g_q);
    cudaGetSymbolAddress((void**)&kvp, g_kv);
    cudaGetSymbolAddress((void**)&sp, g_s);

    // 1. splits of inputs
    split_kernel<<<4096, 256>>>(x, xhi, xlo, 4194304);
    split_kernel<<<4096, 256>>>(ctx, chi, clo, 4194304);
    tsplit_kernel<<<dim3(32, 32, 1), 256>>>(Wq, 0, 1024, wqThi, wqTlo, 0, 1024);
    tsplit_kernel<<<dim3(64, 32, 1), 256>>>(Wkv, 0, 2048, wkThi, wkTlo, 0, 1024);

    // 2. projections: q = x@Wq, kv = ctx@Wkv
    gemm_bf16<128, 128, 64, 32><<<dim3(8, 32, 1), 256>>>(
        xhi, xlo, wqThi, wqTlo, qp, 1024, 1024, 1024, 1024,
        1, 0, 0, 0, 0, 0, 0);
    gemm_bf16<128, 128, 64, 32><<<dim3(16, 32, 1), 256>>>(
        chi, clo, wkThi, wkTlo, kvp, 1024, 1024, 1024, 2048,
        1, 0, 0, 0, 0, 0, 0);

    // 3. splits of q, kv; transposed split of v per batch
    split_kernel<<<4096, 256>>>(qp, qhi, qlo, 4194304);
    split_kernel<<<8192, 256>>>(kvp, kvhi, kvlo, 8388608);
    tsplit_kernel<<<dim3(32, 32, 4), 256>>>(kvp + 1024, 2097152, 2048, vThi, vTlo, 1048576, 1024);

    // 4. raw scores per (b,h): S = Q_h K_h^T -> g_s [b][i][h][j]
    gemm_bf16<128, 128, 64, 32><<<dim3(8, 8, 64), 256>>>(
        qhi, qlo, kvhi, kvlo, sp, 64, 1024, 2048, 16384,
        16, 1048576, 64, 2097152, 64, 16777216, 1024);

    // 5+6 fused: softmax + talking-heads mix + LN -> split bf16 w [b,g][i][j]
    int smem_f = 16 * SSTR * 4;
    cudaFuncSetAttribute(softmax_mixln_kernel,
                         cudaFuncAttributeMaxDynamicSharedMemorySize, smem_f);
    softmax_mixln_kernel<<<4096, 256, smem_f>>>(sp, Wt, gamma, beta, whi, wlo);

    // 7. AV per (b,g): out[i][g*64+d] = sum_j w[i][j] v[j][d]
    gemm_bf16<128, 64, 32, 32><<<dim3(1, 8, 64), 256>>>(
        whi, wlo, vThi, vTlo, out, 1024, 1024, 1024, 1024,
        16, 16777216, 1048576, 1048576, 65536, 1048576, 64);
}

// round 13
// speedup vs baseline: 1.1457x; 1.1457x over previous
#include <cuda_runtime.h>
#include <cuda_bf16.h>

using bf16 = __nv_bfloat16;
using bf162 = __nv_bfloat162;

#define SEQ 1024
#define NB 4
#define NH 16
#define HD 64
#define LN_EPS 1e-5f

// ---------------- scratch (device globals; no allocations allowed) ----------
__device__ bf16 g_xhi[4194304],  g_xlo[4194304];     // x split
__device__ bf16 g_chi[4194304],  g_clo[4194304];     // context split
__device__ bf16 g_wqThi[1048576], g_wqTlo[1048576];  // Wq^T  [n][k]
__device__ bf16 g_wkThi[2097152], g_wkTlo[2097152];  // Wkv^T [n][k]
__device__ float g_q[4194304];                        // x@Wq fp32
__device__ float g_kv[8388608];                       // ctx@Wkv fp32 (k|v)
__device__ bf16 g_qhi[4194304],  g_qlo[4194304];
__device__ bf16 g_kvhi[8388608], g_kvlo[8388608];
__device__ bf16 g_vThi[4194304], g_vTlo[4194304];    // v^T per batch [d][j]
__device__ float g_s[67108864];                       // raw scores [b][i][h][j]
__device__ bf16 g_whi[67108864], g_wlo[67108864];    // mixed+LN weights [b,g][i][j]

// ---------------- split fp32 -> bf16 hi/lo ----------------------------------
__global__ __launch_bounds__(256) void split_kernel(
    const float* __restrict__ in, bf16* __restrict__ hi, bf16* __restrict__ lo, int n)
{
    int i = (blockIdx.x * 256 + threadIdx.x) * 4;
    if (i >= n) return;
    float4 v = *(const float4*)(in + i);
    bf16 h0 = __float2bfloat16(v.x), h1 = __float2bfloat16(v.y);
    bf16 h2 = __float2bfloat16(v.z), h3 = __float2bfloat16(v.w);
    bf16 l0 = __float2bfloat16(v.x - __bfloat162float(h0));
    bf16 l1 = __float2bfloat16(v.y - __bfloat162float(h1));
    bf16 l2 = __float2bfloat16(v.z - __bfloat162float(h2));
    bf16 l3 = __float2bfloat16(v.w - __bfloat162float(h3));
    bf162 p;
    p.x = h0; p.y = h1; *(bf162*)(hi + i)     = p;
    p.x = h2; p.y = h3; *(bf162*)(hi + i + 2) = p;
    p.x = l0; p.y = l1; *(bf162*)(lo + i)     = p;
    p.x = l2; p.y = l3; *(bf162*)(lo + i + 2) = p;
}

// ---------------- transpose + split: out[c][r] = in[r][c] -------------------
__global__ __launch_bounds__(256) void tsplit_kernel(
    const float* __restrict__ in, long inZ, int inStride,
    bf16* __restrict__ hi, bf16* __restrict__ lo, long outZ, int outStride)
{
    __shared__ float tile[32][33];
    const float* ip = in + (long)blockIdx.z * inZ;
    int r0 = blockIdx.y * 32, c0 = blockIdx.x * 32;
    int t = threadIdx.x;
    {
        int r = t >> 3, c4 = (t & 7) * 4;
        float4 v = *(const float4*)(ip + (long)(r0 + r) * inStride + c0 + c4);
        tile[r][c4] = v.x; tile[r][c4 + 1] = v.y; tile[r][c4 + 2] = v.z; tile[r][c4 + 3] = v.w;
    }
    __syncthreads();
    int c = t >> 3, r4 = (t & 7) * 4;
    long ob = (long)blockIdx.z * outZ + (long)(c0 + c) * outStride + r0 + r4;
    float f0 = tile[r4][c], f1 = tile[r4 + 1][c], f2 = tile[r4 + 2][c], f3 = tile[r4 + 3][c];
    bf16 h0 = __float2bfloat16(f0), h1 = __float2bfloat16(f1);
    bf16 h2 = __float2bfloat16(f2), h3 = __float2bfloat16(f3);
    bf162 p;
    p.x = h0; p.y = h1; *(bf162*)(hi + ob)     = p;
    p.x = h2; p.y = h3; *(bf162*)(hi + ob + 2) = p;
    p.x = __float2bfloat16(f0 - __bfloat162float(h0));
    p.y = __float2bfloat16(f1 - __bfloat162float(h1));
    *(bf162*)(lo + ob) = p;
    p.x = __float2bfloat16(f2 - __bfloat162float(h2));
    p.y = __float2bfloat16(f3 - __bfloat162float(h3));
    *(bf162*)(lo + ob + 2) = p;
}

// ---------------- mma.sync helper -------------------------------------------
__device__ __forceinline__ void mma16816(float* d, const unsigned* a, unsigned b0, unsigned b1)
{
    asm volatile(
        "mma.sync.aligned.m16n8k16.row.col.f32.bf16.bf16.f32 "
        "{%0,%1,%2,%3}, {%4,%5,%6,%7}, {%8,%9}, {%0,%1,%2,%3};\n"
        : "+f"(d[0]), "+f"(d[1]), "+f"(d[2]), "+f"(d[3])
        : "r"(a[0]), "r"(a[1]), "r"(a[2]), "r"(a[3]), "r"(b0), "r"(b1));
}

// ---------------- split-bf16 GEMM: C[m][n] = sum_k A[m][k] * B[n][k] --------
template <int BM, int BNt, int WM, int WNt>
__global__ __launch_bounds__(256) void gemm_bf16(
    const bf16* __restrict__ Ahi, const bf16* __restrict__ Alo,
    const bf16* __restrict__ Bhi, const bf16* __restrict__ Blo,
    float* __restrict__ C, int K, int lda, int ldb, int ldc,
    int HB, long sA1, long sA2, long sB1, long sB2, long sC1, long sC2)
{
    constexpr int KS = 40;                 // smem stride (bf16 units), conflict-free
    __shared__ bf16 As[2][BM * KS];
    __shared__ bf16 Bs[2][BNt * KS];

    int z = blockIdx.z;
    long zb = z / HB, zr = z % HB;
    const bf16* Ah = Ahi + zb * sA1 + zr * sA2 + (long)(blockIdx.y * BM) * lda;
    const bf16* Al = Alo + zb * sA1 + zr * sA2 + (long)(blockIdx.y * BM) * lda;
    const bf16* Bh = Bhi + zb * sB1 + zr * sB2 + (long)(blockIdx.x * BNt) * ldb;
    const bf16* Bl = Blo + zb * sB1 + zr * sB2 + (long)(blockIdx.x * BNt) * ldb;
    float* Cp = C + zb * sC1 + zr * sC2 + (long)(blockIdx.y * BM) * ldc + blockIdx.x * BNt;

    int t = threadIdx.x, w = t >> 5, lane = t & 31;
    constexpr int MW = BM / WM;
    constexpr int MB = WM / 16, NBk = WNt / 8;
    int mw = (w % MW) * WM, nw = (w / MW) * WNt;
    int fr = lane >> 2, fc = (lane & 3) * 2;

    float acc[MB][NBk][4];
#pragma unroll
    for (int i = 0; i < MB; i++)
#pragma unroll
        for (int j = 0; j < NBk; j++)
#pragma unroll
            for (int e = 0; e < 4; e++) acc[i][j][e] = 0.f;

    for (int k0 = 0; k0 < K; k0 += 32) {
        __syncthreads();
#pragma unroll 2
        for (int i = t; i < BM * 4; i += 256) {
            int m = i >> 2, kv = (i & 3) * 8;
            *(uint4*)&As[0][m * KS + kv] = *(const uint4*)(Ah + (long)m * lda + k0 + kv);
            *(uint4*)&As[1][m * KS + kv] = *(const uint4*)(Al + (long)m * lda + k0 + kv);
        }
#pragma unroll 2
        for (int i = t; i < BNt * 4; i += 256) {
            int n = i >> 2, kv = (i & 3) * 8;
            *(uint4*)&Bs[0][n * KS + kv] = *(const uint4*)(Bh + (long)n * ldb + k0 + kv);
            *(uint4*)&Bs[1][n * KS + kv] = *(const uint4*)(Bl + (long)n * ldb + k0 + kv);
        }
        __syncthreads();
#pragma unroll
        for (int ks = 0; ks < 32; ks += 16) {
            unsigned ah[MB][4], al[MB][4];
#pragma unroll
            for (int mb = 0; mb < MB; mb++) {
                int mbase = mw + mb * 16;
                ah[mb][0] = *(unsigned*)&As[0][(mbase + fr) * KS + ks + fc];
                ah[mb][1] = *(unsigned*)&As[0][(mbase + fr + 8) * KS + ks + fc];
                ah[mb][2] = *(unsigned*)&As[0][(mbase + fr) * KS + ks + fc + 8];
                ah[mb][3] = *(unsigned*)&As[0][(mbase + fr + 8) * KS + ks + fc + 8];
                al[mb][0] = *(unsigned*)&As[1][(mbase + fr) * KS + ks + fc];
                al[mb][1] = *(unsigned*)&As[1][(mbase + fr + 8) * KS + ks + fc];
                al[mb][2] = *(unsigned*)&As[1][(mbase + fr) * KS + ks + fc + 8];
                al[mb][3] = *(unsigned*)&As[1][(mbase + fr + 8) * KS + ks + fc + 8];
            }
#pragma unroll
            for (int nb = 0; nb < NBk; nb++) {
                int nbase = nw + nb * 8 + fr;
                unsigned bh0 = *(unsigned*)&Bs[0][nbase * KS + ks + fc];
                unsigned bh1 = *(unsigned*)&Bs[0][nbase * KS + ks + fc + 8];
                unsigned bl0 = *(unsigned*)&Bs[1][nbase * KS + ks + fc];
                unsigned bl1 = *(unsigned*)&Bs[1][nbase * KS + ks + fc + 8];
#pragma unroll
                for (int mb = 0; mb < MB; mb++) {
                    mma16816(acc[mb][nb], ah[mb], bh0, bh1);  // hi*hi
                    mma16816(acc[mb][nb], ah[mb], bl0, bl1);  // hi*lo
                    mma16816(acc[mb][nb], al[mb], bh0, bh1);  // lo*hi
                }
            }
        }
    }
    // epilogue
#pragma unroll
    for (int mb = 0; mb < MB; mb++)
#pragma unroll
        for (int nb = 0; nb < NBk; nb++) {
            float* cp = Cp + (long)(mw + mb * 16 + fr) * ldc + nw + nb * 8 + fc;
            *(float2*)cp = make_float2(acc[mb][nb][0], acc[mb][nb][1]);
            *(float2*)(cp + (long)8 * ldc) = make_float2(acc[mb][nb][2], acc[mb][nb][3]);
        }
}

// ---------------- FUSED softmax + talking-heads mix + LN (v2) ---------------
// 512 threads = 16 warps; warp w owns head row h = w: loads the raw score row
// straight from gmem into registers, softmaxes via shfl, writes only probs to
// smem. One __syncthreads, then 512 threads do the 16x16 mix + LN (j-pair per
// thread) and emit split-bf16 w [b,g][i][j].
#define SSTR 1032
__global__ __launch_bounds__(512) void softmax_mixln_kernel(
    const float* __restrict__ s, const float* __restrict__ Wt,
    const float* __restrict__ gamma, const float* __restrict__ beta,
    bf16* __restrict__ whi, bf16* __restrict__ wlo)
{
    extern __shared__ float sm[];            // [16][SSTR] probs
    __shared__ float wts[16][17];
    __shared__ float gm[16], bt[16];
    int t = threadIdx.x;
    if (t < 256) wts[t >> 4][t & 15] = Wt[t];
    if (t < 16) { gm[t] = gamma[t]; bt[t] = beta[t]; }

    long bi = blockIdx.x;                    // b*1024 + i
    int w = t >> 5, lane = t & 31;

    // register softmax: warp w handles head row h = w
    {
        const float4* rp4 = (const float4*)(s + bi * 16384 + (long)w * 1024);
        float4 v[8];
        float mx = -1e30f;
#pragma unroll
        for (int it = 0; it < 8; it++) {
            v[it] = rp4[lane + it * 32];
            mx = fmaxf(mx, fmaxf(fmaxf(v[it].x, v[it].y), fmaxf(v[it].z, v[it].w)));
        }
#pragma unroll
        for (int o = 16; o > 0; o >>= 1) mx = fmaxf(mx, __shfl_xor_sync(0xffffffffu, mx, o));
        float sum = 0.f;
#pragma unroll
        for (int it = 0; it < 8; it++) {
            v[it].x = __expf(0.125f * (v[it].x - mx));
            v[it].y = __expf(0.125f * (v[it].y - mx));
            v[it].z = __expf(0.125f * (v[it].z - mx));
            v[it].w = __expf(0.125f * (v[it].w - mx));
            sum += v[it].x + v[it].y + v[it].z + v[it].w;
        }
#pragma unroll
        for (int o = 16; o > 0; o >>= 1) sum += __shfl_xor_sync(0xffffffffu, sum, o);
        float inv = 1.f / sum;
#pragma unroll
        for (int it = 0; it < 8; it++) {
            v[it].x *= inv; v[it].y *= inv; v[it].z *= inv; v[it].w *= inv;
            *(float4*)&sm[w * SSTR + (lane + it * 32) * 4] = v[it];
        }
    }
    __syncthreads();

    // mix + LN: thread t handles j-pair (2t, 2t+1)
    long b = bi >> 10, i = bi & 1023;
    int j0 = t * 2;
    float sv0[16], sv1[16];
#pragma unroll
    for (int h = 0; h < 16; h++) {
        float2 v = *(const float2*)&sm[h * SSTR + j0];
        sv0[h] = v.x; sv1[h] = v.y;
    }
    float m0[16], m1[16], mu0 = 0.f, mu1 = 0.f;
#pragma unroll
    for (int g = 0; g < 16; g++) {
        float a = 0.f, b2 = 0.f;
#pragma unroll
        for (int h = 0; h < 16; h++) {
            a  = fmaf(sv0[h], wts[h][g], a);
            b2 = fmaf(sv1[h], wts[h][g], b2);
        }
        m0[g] = a; m1[g] = b2; mu0 += a; mu1 += b2;
    }
    mu0 *= (1.f / 16.f); mu1 *= (1.f / 16.f);
    float va0 = 0.f, va1 = 0.f;
#pragma unroll
    for (int g = 0; g < 16; g++) {
        float d0 = m0[g] - mu0, d1 = m1[g] - mu1;
        va0 = fmaf(d0, d0, va0); va1 = fmaf(d1, d1, va1);
    }
    float iv0 = rsqrtf(va0 * (1.f / 16.f) + LN_EPS);
    float iv1 = rsqrtf(va1 * (1.f / 16.f) + LN_EPS);
#pragma unroll
    for (int g = 0; g < 16; g++) {
        float w0 = (m0[g] - mu0) * iv0 * gm[g] + bt[g];
        float w1 = (m1[g] - mu1) * iv1 * gm[g] + bt[g];
        bf16 h0 = __float2bfloat16(w0), h1 = __float2bfloat16(w1);
        bf162 ph; ph.x = h0; ph.y = h1;
        bf162 pl;
        pl.x = __float2bfloat16(w0 - __bfloat162float(h0));
        pl.y = __float2bfloat16(w1 - __bfloat162float(h1));
        long ob = ((b * 16 + g) << 20) + (i << 10) + j0;
        *(bf162*)(whi + ob) = ph;
        *(bf162*)(wlo + ob) = pl;
    }
}

// ---------------- driver -----------------------------------------------------
extern "C" void kernel_launch(void* const* d_in, const int* in_sizes, int n_in,
                              void* d_out, int out_size)
{
    const float* x     = (const float*)d_in[0];
    const float* ctx   = (const float*)d_in[1];
    const float* Wq    = (const float*)d_in[2];
    const float* Wkv   = (const float*)d_in[3];
    const float* Wt    = (const float*)d_in[4];
    const float* gamma = (const float*)d_in[5];
    const float* beta  = (const float*)d_in[6];
    float* out = (float*)d_out;

    bf16 *xhi, *xlo, *chi, *clo, *wqThi, *wqTlo, *wkThi, *wkTlo;
    bf16 *qhi, *qlo, *kvhi, *kvlo, *vThi, *vTlo, *whi, *wlo;
    float *qp, *kvp, *sp;
    cudaGetSymbolAddress((void**)&xhi, g_xhi);   cudaGetSymbolAddress((void**)&xlo, g_xlo);
    cudaGetSymbolAddress((void**)&chi, g_chi);   cudaGetSymbolAddress((void**)&clo, g_clo);
    cudaGetSymbolAddress((void**)&wqThi, g_wqThi); cudaGetSymbolAddress((void**)&wqTlo, g_wqTlo);
    cudaGetSymbolAddress((void**)&wkThi, g_wkThi); cudaGetSymbolAddress((void**)&wkTlo, g_wkTlo);
    cudaGetSymbolAddress((void**)&qhi, g_qhi);   cudaGetSymbolAddress((void**)&qlo, g_qlo);
    cudaGetSymbolAddress((void**)&kvhi, g_kvhi); cudaGetSymbolAddress((void**)&kvlo, g_kvlo);
    cudaGetSymbolAddress((void**)&vThi, g_vThi); cudaGetSymbolAddress((void**)&vTlo, g_vTlo);
    cudaGetSymbolAddress((void**)&whi, g_whi);   cudaGetSymbolAddress((void**)&wlo, g_wlo);
    cudaGetSymbolAddress((void**)&qp, g_q);
    cudaGetSymbolAddress((void**)&kvp, g_kv);
    cudaGetSymbolAddress((void**)&sp, g_s);

    // 1. splits of inputs
    split_kernel<<<4096, 256>>>(x, xhi, xlo, 4194304);
    split_kernel<<<4096, 256>>>(ctx, chi, clo, 4194304);
    tsplit_kernel<<<dim3(32, 32, 1), 256>>>(Wq, 0, 1024, wqThi, wqTlo, 0, 1024);
    tsplit_kernel<<<dim3(64, 32, 1), 256>>>(Wkv, 0, 2048, wkThi, wkTlo, 0, 1024);

    // 2. projections: q = x@Wq, kv = ctx@Wkv
    gemm_bf16<128, 128, 64, 32><<<dim3(8, 32, 1), 256>>>(
        xhi, xlo, wqThi, wqTlo, qp, 1024, 1024, 1024, 1024,
        1, 0, 0, 0, 0, 0, 0);
    gemm_bf16<128, 128, 64, 32><<<dim3(16, 32, 1), 256>>>(
        chi, clo, wkThi, wkTlo, kvp, 1024, 1024, 1024, 2048,
        1, 0, 0, 0, 0, 0, 0);

    // 3. splits of q, kv; transposed split of v per batch
    split_kernel<<<4096, 256>>>(qp, qhi, qlo, 4194304);
    split_kernel<<<8192, 256>>>(kvp, kvhi, kvlo, 8388608);
    tsplit_kernel<<<dim3(32, 32, 4), 256>>>(kvp + 1024, 2097152, 2048, vThi, vTlo, 1048576, 1024);

    // 4. raw scores per (b,h): S = Q_h K_h^T -> g_s [b][i][h][j]
    gemm_bf16<128, 128, 64, 32><<<dim3(8, 8, 64), 256>>>(
        qhi, qlo, kvhi, kvlo, sp, 64, 1024, 2048, 16384,
        16, 1048576, 64, 2097152, 64, 16777216, 1024);

    // 5+6 fused v2: softmax + talking-heads mix + LN (512 thr, 1 sync)
    int smem_f = 16 * SSTR * 4;
    cudaFuncSetAttribute(softmax_mixln_kernel,
                         cudaFuncAttributeMaxDynamicSharedMemorySize, smem_f);
    softmax_mixln_kernel<<<4096, 512, smem_f>>>(sp, Wt, gamma, beta, whi, wlo);

    // 7. AV per (b,g): out[i][g*64+d] = sum_j w[i][j] v[j][d]
    gemm_bf16<128, 64, 32, 32><<<dim3(1, 8, 64), 256>>>(
        whi, wlo, vThi, vTlo, out, 1024, 1024, 1024, 1024,
        16, 16777216, 1048576, 1048576, 65536, 1048576, 64);
}

// round 14
// speedup vs baseline: 1.3628x; 1.1895x over previous
#include <cuda_runtime.h>
#include <cuda_bf16.h>

using bf16 = __nv_bfloat16;
using bf162 = __nv_bfloat162;

#define SEQ 1024
#define NB 4
#define NH 16
#define HD 64
#define LN_EPS 1e-5f

// ---------------- scratch (device globals; no allocations allowed) ----------
__device__ bf16 g_xhi[4194304],  g_xlo[4194304];     // x split
__device__ bf16 g_chi[4194304],  g_clo[4194304];     // context split
__device__ bf16 g_wqThi[1048576], g_wqTlo[1048576];  // Wq^T  [n][k]
__device__ bf16 g_wkThi[2097152], g_wkTlo[2097152];  // Wkv^T [n][k]
__device__ float g_q[4194304];                        // x@Wq fp32
__device__ float g_kv[8388608];                       // ctx@Wkv fp32 (k|v)
__device__ bf16 g_qhi[4194304],  g_qlo[4194304];
__device__ bf16 g_kvhi[8388608], g_kvlo[8388608];
__device__ bf16 g_vThi[4194304], g_vTlo[4194304];    // v^T per batch [d][j]
__device__ float g_s[67108864];                       // raw scores [b][i][h][j]
__device__ bf16 g_whi[67108864], g_wlo[67108864];    // mixed+LN weights [b,g][i][j]

// ---------------- split fp32 -> bf16 hi/lo ----------------------------------
__global__ __launch_bounds__(256) void split_kernel(
    const float* __restrict__ in, bf16* __restrict__ hi, bf16* __restrict__ lo, int n)
{
    int i = (blockIdx.x * 256 + threadIdx.x) * 4;
    if (i >= n) return;
    float4 v = *(const float4*)(in + i);
    bf16 h0 = __float2bfloat16(v.x), h1 = __float2bfloat16(v.y);
    bf16 h2 = __float2bfloat16(v.z), h3 = __float2bfloat16(v.w);
    bf16 l0 = __float2bfloat16(v.x - __bfloat162float(h0));
    bf16 l1 = __float2bfloat16(v.y - __bfloat162float(h1));
    bf16 l2 = __float2bfloat16(v.z - __bfloat162float(h2));
    bf16 l3 = __float2bfloat16(v.w - __bfloat162float(h3));
    bf162 p;
    p.x = h0; p.y = h1; *(bf162*)(hi + i)     = p;
    p.x = h2; p.y = h3; *(bf162*)(hi + i + 2) = p;
    p.x = l0; p.y = l1; *(bf162*)(lo + i)     = p;
    p.x = l2; p.y = l3; *(bf162*)(lo + i + 2) = p;
}

// ---------------- transpose + split: out[c][r] = in[r][c] -------------------
__global__ __launch_bounds__(256) void tsplit_kernel(
    const float* __restrict__ in, long inZ, int inStride,
    bf16* __restrict__ hi, bf16* __restrict__ lo, long outZ, int outStride)
{
    __shared__ float tile[32][33];
    const float* ip = in + (long)blockIdx.z * inZ;
    int r0 = blockIdx.y * 32, c0 = blockIdx.x * 32;
    int t = threadIdx.x;
    {
        int r = t >> 3, c4 = (t & 7) * 4;
        float4 v = *(const float4*)(ip + (long)(r0 + r) * inStride + c0 + c4);
        tile[r][c4] = v.x; tile[r][c4 + 1] = v.y; tile[r][c4 + 2] = v.z; tile[r][c4 + 3] = v.w;
    }
    __syncthreads();
    int c = t >> 3, r4 = (t & 7) * 4;
    long ob = (long)blockIdx.z * outZ + (long)(c0 + c) * outStride + r0 + r4;
    float f0 = tile[r4][c], f1 = tile[r4 + 1][c], f2 = tile[r4 + 2][c], f3 = tile[r4 + 3][c];
    bf16 h0 = __float2bfloat16(f0), h1 = __float2bfloat16(f1);
    bf16 h2 = __float2bfloat16(f2), h3 = __float2bfloat16(f3);
    bf162 p;
    p.x = h0; p.y = h1; *(bf162*)(hi + ob)     = p;
    p.x = h2; p.y = h3; *(bf162*)(hi + ob + 2) = p;
    p.x = __float2bfloat16(f0 - __bfloat162float(h0));
    p.y = __float2bfloat16(f1 - __bfloat162float(h1));
    *(bf162*)(lo + ob) = p;
    p.x = __float2bfloat16(f2 - __bfloat162float(h2));
    p.y = __float2bfloat16(f3 - __bfloat162float(h3));
    *(bf162*)(lo + ob + 2) = p;
}

// ---------------- mma.sync + cp.async helpers --------------------------------
__device__ __forceinline__ void mma16816(float* d, const unsigned* a, unsigned b0, unsigned b1)
{
    asm volatile(
        "mma.sync.aligned.m16n8k16.row.col.f32.bf16.bf16.f32 "
        "{%0,%1,%2,%3}, {%4,%5,%6,%7}, {%8,%9}, {%0,%1,%2,%3};\n"
        : "+f"(d[0]), "+f"(d[1]), "+f"(d[2]), "+f"(d[3])
        : "r"(a[0]), "r"(a[1]), "r"(a[2]), "r"(a[3]), "r"(b0), "r"(b1));
}

__device__ __forceinline__ void cp16(bf16* sptr, const bf16* gptr)
{
    unsigned sa = (unsigned)__cvta_generic_to_shared(sptr);
    asm volatile("cp.async.cg.shared.global [%0], [%1], 16;\n" :: "r"(sa), "l"(gptr));
}
#define CP_COMMIT() asm volatile("cp.async.commit_group;\n" ::: "memory")
#define CP_WAIT1()  asm volatile("cp.async.wait_group 1;\n" ::: "memory")
#define CP_WAIT0()  asm volatile("cp.async.wait_group 0;\n" ::: "memory")

// ---------------- split-bf16 GEMM: C[m][n] = sum_k A[m][k] * B[n][k] --------
// 2-stage cp.async double-buffered. A,B hi/lo bf16; 3-term split; fp32 accum.
template <int BM, int BNt, int WM, int WNt>
__global__ __launch_bounds__(256) void gemm_bf16(
    const bf16* __restrict__ Ahi, const bf16* __restrict__ Alo,
    const bf16* __restrict__ Bhi, const bf16* __restrict__ Blo,
    float* __restrict__ C, int K, int lda, int ldb, int ldc,
    int HB, long sA1, long sA2, long sB1, long sB2, long sC1, long sC2)
{
    constexpr int KS = 40;                 // smem stride (bf16), conflict-free
    constexpr int ATILE = BM * KS;
    constexpr int BTILE = BNt * KS;
    constexpr int STG = 2 * ATILE + 2 * BTILE;
    extern __shared__ bf16 smem[];

    int z = blockIdx.z;
    long zb = z / HB, zr = z % HB;
    const bf16* Ah = Ahi + zb * sA1 + zr * sA2 + (long)(blockIdx.y * BM) * lda;
    const bf16* Al = Alo + zb * sA1 + zr * sA2 + (long)(blockIdx.y * BM) * lda;
    const bf16* Bh = Bhi + zb * sB1 + zr * sB2 + (long)(blockIdx.x * BNt) * ldb;
    const bf16* Bl = Blo + zb * sB1 + zr * sB2 + (long)(blockIdx.x * BNt) * ldb;
    float* Cp = C + zb * sC1 + zr * sC2 + (long)(blockIdx.y * BM) * ldc + blockIdx.x * BNt;

    int t = threadIdx.x, w = t >> 5, lane = t & 31;
    constexpr int MW = BM / WM;
    constexpr int MB = WM / 16, NBk = WNt / 8;
    int mw = (w % MW) * WM, nw = (w / MW) * WNt;
    int fr = lane >> 2, fc = (lane & 3) * 2;

    // async tile loader into stage st
    auto load_tile = [&](int k0, int st) {
        bf16* aH = smem + st * STG;
        bf16* aL = aH + ATILE;
        bf16* bH = aL + ATILE;
        bf16* bL = bH + BTILE;
#pragma unroll 2
        for (int i = t; i < BM * 4; i += 256) {
            int m = i >> 2, kv = (i & 3) * 8;
            cp16(aH + m * KS + kv, Ah + (long)m * lda + k0 + kv);
            cp16(aL + m * KS + kv, Al + (long)m * lda + k0 + kv);
        }
#pragma unroll 2
        for (int i = t; i < BNt * 4; i += 256) {
            int n = i >> 2, kv = (i & 3) * 8;
            cp16(bH + n * KS + kv, Bh + (long)n * ldb + k0 + kv);
            cp16(bL + n * KS + kv, Bl + (long)n * ldb + k0 + kv);
        }
        CP_COMMIT();
    };

    float acc[MB][NBk][4];
#pragma unroll
    for (int i = 0; i < MB; i++)
#pragma unroll
        for (int j = 0; j < NBk; j++)
#pragma unroll
            for (int e = 0; e < 4; e++) acc[i][j][e] = 0.f;

    load_tile(0, 0);
    int st = 0;
    for (int k0 = 0; k0 < K; k0 += 32, st ^= 1) {
        bool more = (k0 + 32 < K);
        if (more) load_tile(k0 + 32, st ^ 1);
        if (more) CP_WAIT1(); else CP_WAIT0();
        __syncthreads();

        const bf16* aH = smem + st * STG;
        const bf16* aL = aH + ATILE;
        const bf16* bH = aL + ATILE;
        const bf16* bL = bH + BTILE;
#pragma unroll
        for (int ks = 0; ks < 32; ks += 16) {
            unsigned ah[MB][4], al[MB][4];
#pragma unroll
            for (int mb = 0; mb < MB; mb++) {
                int mbase = mw + mb * 16;
                ah[mb][0] = *(const unsigned*)&aH[(mbase + fr) * KS + ks + fc];
                ah[mb][1] = *(const unsigned*)&aH[(mbase + fr + 8) * KS + ks + fc];
                ah[mb][2] = *(const unsigned*)&aH[(mbase + fr) * KS + ks + fc + 8];
                ah[mb][3] = *(const unsigned*)&aH[(mbase + fr + 8) * KS + ks + fc + 8];
                al[mb][0] = *(const unsigned*)&aL[(mbase + fr) * KS + ks + fc];
                al[mb][1] = *(const unsigned*)&aL[(mbase + fr + 8) * KS + ks + fc];
                al[mb][2] = *(const unsigned*)&aL[(mbase + fr) * KS + ks + fc + 8];
                al[mb][3] = *(const unsigned*)&aL[(mbase + fr + 8) * KS + ks + fc + 8];
            }
#pragma unroll
            for (int nb = 0; nb < NBk; nb++) {
                int nbase = nw + nb * 8 + fr;
                unsigned bh0 = *(const unsigned*)&bH[nbase * KS + ks + fc];
                unsigned bh1 = *(const unsigned*)&bH[nbase * KS + ks + fc + 8];
                unsigned bl0 = *(const unsigned*)&bL[nbase * KS + ks + fc];
                unsigned bl1 = *(const unsigned*)&bL[nbase * KS + ks + fc + 8];
#pragma unroll
                for (int mb = 0; mb < MB; mb++) {
                    mma16816(acc[mb][nb], ah[mb], bh0, bh1);  // hi*hi
                    mma16816(acc[mb][nb], ah[mb], bl0, bl1);  // hi*lo
                    mma16816(acc[mb][nb], al[mb], bh0, bh1);  // lo*hi
                }
            }
        }
        __syncthreads();
    }
    // epilogue
#pragma unroll
    for (int mb = 0; mb < MB; mb++)
#pragma unroll
        for (int nb = 0; nb < NBk; nb++) {
            float* cp = Cp + (long)(mw + mb * 16 + fr) * ldc + nw + nb * 8 + fc;
            *(float2*)cp = make_float2(acc[mb][nb][0], acc[mb][nb][1]);
            *(float2*)(cp + (long)8 * ldc) = make_float2(acc[mb][nb][2], acc[mb][nb][3]);
        }
}

// ---------------- FUSED softmax + talking-heads mix + LN (v2) ---------------
#define SSTR 1032
__global__ __launch_bounds__(512) void softmax_mixln_kernel(
    const float* __restrict__ s, const float* __restrict__ Wt,
    const float* __restrict__ gamma, const float* __restrict__ beta,
    bf16* __restrict__ whi, bf16* __restrict__ wlo)
{
    extern __shared__ float sm[];            // [16][SSTR] probs
    __shared__ float wts[16][17];
    __shared__ float gm[16], bt[16];
    int t = threadIdx.x;
    if (t < 256) wts[t >> 4][t & 15] = Wt[t];
    if (t < 16) { gm[t] = gamma[t]; bt[t] = beta[t]; }

    long bi = blockIdx.x;                    // b*1024 + i
    int w = t >> 5, lane = t & 31;

    // register softmax: warp w handles head row h = w
    {
        const float4* rp4 = (const float4*)(s + bi * 16384 + (long)w * 1024);
        float4 v[8];
        float mx = -1e30f;
#pragma unroll
        for (int it = 0; it < 8; it++) {
            v[it] = rp4[lane + it * 32];
            mx = fmaxf(mx, fmaxf(fmaxf(v[it].x, v[it].y), fmaxf(v[it].z, v[it].w)));
        }
#pragma unroll
        for (int o = 16; o > 0; o >>= 1) mx = fmaxf(mx, __shfl_xor_sync(0xffffffffu, mx, o));
        float sum = 0.f;
#pragma unroll
        for (int it = 0; it < 8; it++) {
            v[it].x = __expf(0.125f * (v[it].x - mx));
            v[it].y = __expf(0.125f * (v[it].y - mx));
            v[it].z = __expf(0.125f * (v[it].z - mx));
            v[it].w = __expf(0.125f * (v[it].w - mx));
            sum += v[it].x + v[it].y + v[it].z + v[it].w;
        }
#pragma unroll
        for (int o = 16; o > 0; o >>= 1) sum += __shfl_xor_sync(0xffffffffu, sum, o);
        float inv = 1.f / sum;
#pragma unroll
        for (int it = 0; it < 8; it++) {
            v[it].x *= inv; v[it].y *= inv; v[it].z *= inv; v[it].w *= inv;
            *(float4*)&sm[w * SSTR + (lane + it * 32) * 4] = v[it];
        }
    }
    __syncthreads();

    // mix + LN: thread t handles j-pair (2t, 2t+1)
    long b = bi >> 10, i = bi & 1023;
    int j0 = t * 2;
    float sv0[16], sv1[16];
#pragma unroll
    for (int h = 0; h < 16; h++) {
        float2 v = *(const float2*)&sm[h * SSTR + j0];
        sv0[h] = v.x; sv1[h] = v.y;
    }
    float m0[16], m1[16], mu0 = 0.f, mu1 = 0.f;
#pragma unroll
    for (int g = 0; g < 16; g++) {
        float a = 0.f, b2 = 0.f;
#pragma unroll
        for (int h = 0; h < 16; h++) {
            a  = fmaf(sv0[h], wts[h][g], a);
            b2 = fmaf(sv1[h], wts[h][g], b2);
        }
        m0[g] = a; m1[g] = b2; mu0 += a; mu1 += b2;
    }
    mu0 *= (1.f / 16.f); mu1 *= (1.f / 16.f);
    float va0 = 0.f, va1 = 0.f;
#pragma unroll
    for (int g = 0; g < 16; g++) {
        float d0 = m0[g] - mu0, d1 = m1[g] - mu1;
        va0 = fmaf(d0, d0, va0); va1 = fmaf(d1, d1, va1);
    }
    float iv0 = rsqrtf(va0 * (1.f / 16.f) + LN_EPS);
    float iv1 = rsqrtf(va1 * (1.f / 16.f) + LN_EPS);
#pragma unroll
    for (int g = 0; g < 16; g++) {
        float w0 = (m0[g] - mu0) * iv0 * gm[g] + bt[g];
        float w1 = (m1[g] - mu1) * iv1 * gm[g] + bt[g];
        bf16 h0 = __float2bfloat16(w0), h1 = __float2bfloat16(w1);
        bf162 ph; ph.x = h0; ph.y = h1;
        bf162 pl;
        pl.x = __float2bfloat16(w0 - __bfloat162float(h0));
        pl.y = __float2bfloat16(w1 - __bfloat162float(h1));
        long ob = ((b * 16 + g) << 20) + (i << 10) + j0;
        *(bf162*)(whi + ob) = ph;
        *(bf162*)(wlo + ob) = pl;
    }
}

// ---------------- driver -----------------------------------------------------
extern "C" void kernel_launch(void* const* d_in, const int* in_sizes, int n_in,
                              void* d_out, int out_size)
{
    const float* x     = (const float*)d_in[0];
    const float* ctx   = (const float*)d_in[1];
    const float* Wq    = (const float*)d_in[2];
    const float* Wkv   = (const float*)d_in[3];
    const float* Wt    = (const float*)d_in[4];
    const float* gamma = (const float*)d_in[5];
    const float* beta  = (const float*)d_in[6];
    float* out = (float*)d_out;

    bf16 *xhi, *xlo, *chi, *clo, *wqThi, *wqTlo, *wkThi, *wkTlo;
    bf16 *qhi, *qlo, *kvhi, *kvlo, *vThi, *vTlo, *whi, *wlo;
    float *qp, *kvp, *sp;
    cudaGetSymbolAddress((void**)&xhi, g_xhi);   cudaGetSymbolAddress((void**)&xlo, g_xlo);
    cudaGetSymbolAddress((void**)&chi, g_chi);   cudaGetSymbolAddress((void**)&clo, g_clo);
    cudaGetSymbolAddress((void**)&wqThi, g_wqThi); cudaGetSymbolAddress((void**)&wqTlo, g_wqTlo);
    cudaGetSymbolAddress((void**)&wkThi, g_wkThi); cudaGetSymbolAddress((void**)&wkTlo, g_wkTlo);
    cudaGetSymbolAddress((void**)&qhi, g_qhi);   cudaGetSymbolAddress((void**)&qlo, g_qlo);
    cudaGetSymbolAddress((void**)&kvhi, g_kvhi); cudaGetSymbolAddress((void**)&kvlo, g_kvlo);
    cudaGetSymbolAddress((void**)&vThi, g_vThi); cudaGetSymbolAddress((void**)&vTlo, g_vTlo);
    cudaGetSymbolAddress((void**)&whi, g_whi);   cudaGetSymbolAddress((void**)&wlo, g_wlo);
    cudaGetSymbolAddress((void**)&qp, g_q);
    cudaGetSymbolAddress((void**)&kvp, g_kv);
    cudaGetSymbolAddress((void**)&sp, g_s);

    // dynamic smem sizes for the two GEMM shapes
    int smem_g1 = (2 * (128 * 40) + 2 * (128 * 40)) * 2 * 2;   // 81920 B
    int smem_g2 = (2 * (128 * 40) + 2 * (64 * 40)) * 2 * 2;    // 61440 B
    cudaFuncSetAttribute(gemm_bf16<128, 128, 64, 32>,
                         cudaFuncAttributeMaxDynamicSharedMemorySize, smem_g1);
    cudaFuncSetAttribute(gemm_bf16<128, 64, 32, 32>,
                         cudaFuncAttributeMaxDynamicSharedMemorySize, smem_g2);

    // 1. splits of inputs
    split_kernel<<<4096, 256>>>(x, xhi, xlo, 4194304);
    split_kernel<<<4096, 256>>>(ctx, chi, clo, 4194304);
    tsplit_kernel<<<dim3(32, 32, 1), 256>>>(Wq, 0, 1024, wqThi, wqTlo, 0, 1024);
    tsplit_kernel<<<dim3(64, 32, 1), 256>>>(Wkv, 0, 2048, wkThi, wkTlo, 0, 1024);

    // 2. projections: q = x@Wq, kv = ctx@Wkv
    gemm_bf16<128, 128, 64, 32><<<dim3(8, 32, 1), 256, smem_g1>>>(
        xhi, xlo, wqThi, wqTlo, qp, 1024, 1024, 1024, 1024,
        1, 0, 0, 0, 0, 0, 0);
    gemm_bf16<128, 128, 64, 32><<<dim3(16, 32, 1), 256, smem_g1>>>(
        chi, clo, wkThi, wkTlo, kvp, 1024, 1024, 1024, 2048,
        1, 0, 0, 0, 0, 0, 0);

    // 3. splits of q, kv; transposed split of v per batch
    split_kernel<<<4096, 256>>>(qp, qhi, qlo, 4194304);
    split_kernel<<<8192, 256>>>(kvp, kvhi, kvlo, 8388608);
    tsplit_kernel<<<dim3(32, 32, 4), 256>>>(kvp + 1024, 2097152, 2048, vThi, vTlo, 1048576, 1024);

    // 4. raw scores per (b,h): S = Q_h K_h^T -> g_s [b][i][h][j]
    gemm_bf16<128, 128, 64, 32><<<dim3(8, 8, 64), 256, smem_g1>>>(
        qhi, qlo, kvhi, kvlo, sp, 64, 1024, 2048, 16384,
        16, 1048576, 64, 2097152, 64, 16777216, 1024);

    // 5+6 fused v2: softmax + talking-heads mix + LN (512 thr, 1 sync)
    int smem_f = 16 * SSTR * 4;
    cudaFuncSetAttribute(softmax_mixln_kernel,
                         cudaFuncAttributeMaxDynamicSharedMemorySize, smem_f);
    softmax_mixln_kernel<<<4096, 512, smem_f>>>(sp, Wt, gamma, beta, whi, wlo);

    // 7. AV per (b,g): out[i][g*64+d] = sum_j w[i][j] v[j][d]
    gemm_bf16<128, 64, 32, 32><<<dim3(1, 8, 64), 256, smem_g2>>>(
        whi, wlo, vThi, vTlo, out, 1024, 1024, 1024, 1024,
        16, 16777216, 1048576, 1048576, 65536, 1048576, 64);
}

// round 17
// speedup vs baseline: 1.3742x; 1.0084x over previous
#include <cuda_runtime.h>
#include <cuda_bf16.h>

using bf16 = __nv_bfloat16;
using bf162 = __nv_bfloat162;

#define SEQ 1024
#define NB 4
#define NH 16
#define HD 64
#define LN_EPS 1e-5f

// ---------------- scratch (device globals; no allocations allowed) ----------
__device__ bf16 g_xhi[4194304],  g_xlo[4194304];     // x split
__device__ bf16 g_chi[4194304],  g_clo[4194304];     // context split
__device__ bf16 g_wqThi[1048576], g_wqTlo[1048576];  // Wq^T  [n][k]
__device__ bf16 g_wkThi[2097152], g_wkTlo[2097152];  // Wkv^T [n][k]
__device__ bf16 g_qhi[4194304],  g_qlo[4194304];     // q split (from GEMM epilogue)
__device__ bf16 g_kvhi[8388608], g_kvlo[8388608];    // kv split (from GEMM epilogue)
__device__ bf16 g_vThi[4194304], g_vTlo[4194304];    // v^T per batch [d][j]
__device__ float g_s[67108864];                       // raw scores [b][i][h][j]
__device__ bf16 g_whi[67108864], g_wlo[67108864];    // mixed+LN weights [b,g][i][j]

// ---------------- split fp32 -> bf16 hi/lo ----------------------------------
__global__ __launch_bounds__(256) void split_kernel(
    const float* __restrict__ in, bf16* __restrict__ hi, bf16* __restrict__ lo, int n)
{
    int i = (blockIdx.x * 256 + threadIdx.x) * 4;
    if (i >= n) return;
    float4 v = *(const float4*)(in + i);
    bf16 h0 = __float2bfloat16(v.x), h1 = __float2bfloat16(v.y);
    bf16 h2 = __float2bfloat16(v.z), h3 = __float2bfloat16(v.w);
    bf16 l0 = __float2bfloat16(v.x - __bfloat162float(h0));
    bf16 l1 = __float2bfloat16(v.y - __bfloat162float(h1));
    bf16 l2 = __float2bfloat16(v.z - __bfloat162float(h2));
    bf16 l3 = __float2bfloat16(v.w - __bfloat162float(h3));
    bf162 p;
    p.x = h0; p.y = h1; *(bf162*)(hi + i)     = p;
    p.x = h2; p.y = h3; *(bf162*)(hi + i + 2) = p;
    p.x = l0; p.y = l1; *(bf162*)(lo + i)     = p;
    p.x = l2; p.y = l3; *(bf162*)(lo + i + 2) = p;
}

// ---------------- transpose + split fp32 in: out[c][r] = in[r][c] -----------
__global__ __launch_bounds__(256) void tsplit_kernel(
    const float* __restrict__ in, long inZ, int inStride,
    bf16* __restrict__ hi, bf16* __restrict__ lo, long outZ, int outStride)
{
    __shared__ float tile[32][33];
    const float* ip = in + (long)blockIdx.z * inZ;
    int r0 = blockIdx.y * 32, c0 = blockIdx.x * 32;
    int t = threadIdx.x;
    {
        int r = t >> 3, c4 = (t & 7) * 4;
        float4 v = *(const float4*)(ip + (long)(r0 + r) * inStride + c0 + c4);
        tile[r][c4] = v.x; tile[r][c4 + 1] = v.y; tile[r][c4 + 2] = v.z; tile[r][c4 + 3] = v.w;
    }
    __syncthreads();
    int c = t >> 3, r4 = (t & 7) * 4;
    long ob = (long)blockIdx.z * outZ + (long)(c0 + c) * outStride + r0 + r4;
    float f0 = tile[r4][c], f1 = tile[r4 + 1][c], f2 = tile[r4 + 2][c], f3 = tile[r4 + 3][c];
    bf16 h0 = __float2bfloat16(f0), h1 = __float2bfloat16(f1);
    bf16 h2 = __float2bfloat16(f2), h3 = __float2bfloat16(f3);
    bf162 p;
    p.x = h0; p.y = h1; *(bf162*)(hi + ob)     = p;
    p.x = h2; p.y = h3; *(bf162*)(hi + ob + 2) = p;
    p.x = __float2bfloat16(f0 - __bfloat162float(h0));
    p.y = __float2bfloat16(f1 - __bfloat162float(h1));
    *(bf162*)(lo + ob) = p;
    p.x = __float2bfloat16(f2 - __bfloat162float(h2));
    p.y = __float2bfloat16(f3 - __bfloat162float(h3));
    *(bf162*)(lo + ob + 2) = p;
}

// ---------------- bf16 pair transpose: out[c][r] = in[r][c] (hi & lo) -------
__global__ __launch_bounds__(256) void tbf16_kernel(
    const bf16* __restrict__ inh, const bf16* __restrict__ inl, long inZ, int inStride,
    bf16* __restrict__ outh, bf16* __restrict__ outl, long outZ, int outStride)
{
    __shared__ unsigned short th[32][36];
    __shared__ unsigned short tl[32][36];
    const unsigned short* iph = (const unsigned short*)inh + (long)blockIdx.z * inZ;
    const unsigned short* ipl = (const unsigned short*)inl + (long)blockIdx.z * inZ;
    int r0 = blockIdx.y * 32, c0 = blockIdx.x * 32;
    int t = threadIdx.x;
    {
        int r = t >> 3, c4 = (t & 7) * 4;
        *(ushort4*)&th[r][c4] = *(const ushort4*)(iph + (long)(r0 + r) * inStride + c0 + c4);
        *(ushort4*)&tl[r][c4] = *(const ushort4*)(ipl + (long)(r0 + r) * inStride + c0 + c4);
    }
    __syncthreads();
    int c = t >> 3, r4 = (t & 7) * 4;
    long ob = (long)blockIdx.z * outZ + (long)(c0 + c) * outStride + r0 + r4;
    ushort4 oh, ol;
    oh.x = th[r4][c]; oh.y = th[r4 + 1][c]; oh.z = th[r4 + 2][c]; oh.w = th[r4 + 3][c];
    ol.x = tl[r4][c]; ol.y = tl[r4 + 1][c]; ol.z = tl[r4 + 2][c]; ol.w = tl[r4 + 3][c];
    *(ushort4*)((unsigned short*)outh + ob) = oh;
    *(ushort4*)((unsigned short*)outl + ob) = ol;
}

// ---------------- mma.sync + cp.async helpers --------------------------------
__device__ __forceinline__ void mma16816(float* d, const unsigned* a, unsigned b0, unsigned b1)
{
    asm volatile(
        "mma.sync.aligned.m16n8k16.row.col.f32.bf16.bf16.f32 "
        "{%0,%1,%2,%3}, {%4,%5,%6,%7}, {%8,%9}, {%0,%1,%2,%3};\n"
        : "+f"(d[0]), "+f"(d[1]), "+f"(d[2]), "+f"(d[3])
        : "r"(a[0]), "r"(a[1]), "r"(a[2]), "r"(a[3]), "r"(b0), "r"(b1));
}

__device__ __forceinline__ void cp16(bf16* sptr, const bf16* gptr)
{
    unsigned sa = (unsigned)__cvta_generic_to_shared(sptr);
    asm volatile("cp.async.cg.shared.global [%0], [%1], 16;\n" :: "r"(sa), "l"(gptr));
}
#define CP_COMMIT() asm volatile("cp.async.commit_group;\n" ::: "memory")
#define CP_WAIT1()  asm volatile("cp.async.wait_group 1;\n" ::: "memory")
#define CP_WAIT0()  asm volatile("cp.async.wait_group 0;\n" ::: "memory")

// ---------------- split-bf16 GEMM: C[m][n] = sum_k A[m][k] * B[n][k] --------
// 2-stage cp.async double-buffered; 3-term split; fp32 accum.
// SPLIT_OUT: epilogue emits hi/lo bf16 (Chi/Clo) instead of fp32 C.
template <int BM, int BNt, int WM, int WNt, bool SPLIT_OUT>
__global__ __launch_bounds__(256) void gemm_bf16(
    const bf16* __restrict__ Ahi, const bf16* __restrict__ Alo,
    const bf16* __restrict__ Bhi, const bf16* __restrict__ Blo,
    float* __restrict__ C, bf16* __restrict__ Chi, bf16* __restrict__ Clo,
    int K, int lda, int ldb, int ldc,
    int HB, long sA1, long sA2, long sB1, long sB2, long sC1, long sC2)
{
    constexpr int KS = 40;                 // smem stride (bf16), conflict-free
    constexpr int ATILE = BM * KS;
    constexpr int BTILE = BNt * KS;
    constexpr int STG = 2 * ATILE + 2 * BTILE;
    extern __shared__ bf16 smem[];

    int z = blockIdx.z;
    long zb = z / HB, zr = z % HB;
    const bf16* Ah = Ahi + zb * sA1 + zr * sA2 + (long)(blockIdx.y * BM) * lda;
    const bf16* Al = Alo + zb * sA1 + zr * sA2 + (long)(blockIdx.y * BM) * lda;
    const bf16* Bh = Bhi + zb * sB1 + zr * sB2 + (long)(blockIdx.x * BNt) * ldb;
    const bf16* Bl = Blo + zb * sB1 + zr * sB2 + (long)(blockIdx.x * BNt) * ldb;
    long cbase = zb * sC1 + zr * sC2 + (long)(blockIdx.y * BM) * ldc + blockIdx.x * BNt;

    int t = threadIdx.x, w = t >> 5, lane = t & 31;
    constexpr int MW = BM / WM;
    constexpr int MB = WM / 16, NBk = WNt / 8;
    int mw = (w % MW) * WM, nw = (w / MW) * WNt;
    int fr = lane >> 2, fc = (lane & 3) * 2;

    auto load_tile = [&](int k0, int st) {
        bf16* aH = smem + st * STG;
        bf16* aL = aH + ATILE;
        bf16* bH = aL + ATILE;
        bf16* bL = bH + BTILE;
#pragma unroll 2
        for (int i = t; i < BM * 4; i += 256) {
            int m = i >> 2, kv = (i & 3) * 8;
            cp16(aH + m * KS + kv, Ah + (long)m * lda + k0 + kv);
            cp16(aL + m * KS + kv, Al + (long)m * lda + k0 + kv);
        }
#pragma unroll 2
        for (int i = t; i < BNt * 4; i += 256) {
            int n = i >> 2, kv = (i & 3) * 8;
            cp16(bH + n * KS + kv, Bh + (long)n * ldb + k0 + kv);
            cp16(bL + n * KS + kv, Bl + (long)n * ldb + k0 + kv);
        }
        CP_COMMIT();
    };

    float acc[MB][NBk][4];
#pragma unroll
    for (int i = 0; i < MB; i++)
#pragma unroll
        for (int j = 0; j < NBk; j++)
#pragma unroll
            for (int e = 0; e < 4; e++) acc[i][j][e] = 0.f;

    load_tile(0, 0);
    int st = 0;
    for (int k0 = 0; k0 < K; k0 += 32, st ^= 1) {
        bool more = (k0 + 32 < K);
        if (more) load_tile(k0 + 32, st ^ 1);
        if (more) CP_WAIT1(); else CP_WAIT0();
        __syncthreads();

        const bf16* aH = smem + st * STG;
        const bf16* aL = aH + ATILE;
        const bf16* bH = aL + ATILE;
        const bf16* bL = bH + BTILE;
#pragma unroll
        for (int ks = 0; ks < 32; ks += 16) {
            unsigned ah[MB][4], al[MB][4];
#pragma unroll
            for (int mb = 0; mb < MB; mb++) {
                int mbase = mw + mb * 16;
                ah[mb][0] = *(const unsigned*)&aH[(mbase + fr) * KS + ks + fc];
                ah[mb][1] = *(const unsigned*)&aH[(mbase + fr + 8) * KS + ks + fc];
                ah[mb][2] = *(const unsigned*)&aH[(mbase + fr) * KS + ks + fc + 8];
                ah[mb][3] = *(const unsigned*)&aH[(mbase + fr + 8) * KS + ks + fc + 8];
                al[mb][0] = *(const unsigned*)&aL[(mbase + fr) * KS + ks + fc];
                al[mb][1] = *(const unsigned*)&aL[(mbase + fr + 8) * KS + ks + fc];
                al[mb][2] = *(const unsigned*)&aL[(mbase + fr) * KS + ks + fc + 8];
                al[mb][3] = *(const unsigned*)&aL[(mbase + fr + 8) * KS + ks + fc + 8];
            }
#pragma unroll
            for (int nb = 0; nb < NBk; nb++) {
                int nbase = nw + nb * 8 + fr;
                unsigned bh0 = *(const unsigned*)&bH[nbase * KS + ks + fc];
                unsigned bh1 = *(const unsigned*)&bH[nbase * KS + ks + fc + 8];
                unsigned bl0 = *(const unsigned*)&bL[nbase * KS + ks + fc];
                unsigned bl1 = *(const unsigned*)&bL[nbase * KS + ks + fc + 8];
#pragma unroll
                for (int mb = 0; mb < MB; mb++) {
                    mma16816(acc[mb][nb], ah[mb], bh0, bh1);  // hi*hi
                    mma16816(acc[mb][nb], ah[mb], bl0, bl1);  // hi*lo
                    mma16816(acc[mb][nb], al[mb], bh0, bh1);  // lo*hi
                }
            }
        }
        __syncthreads();
    }
    // epilogue
#pragma unroll
    for (int mb = 0; mb < MB; mb++)
#pragma unroll
        for (int nb = 0; nb < NBk; nb++) {
            long o0 = cbase + (long)(mw + mb * 16 + fr) * ldc + nw + nb * 8 + fc;
            long o1 = o0 + (long)8 * ldc;
            if constexpr (SPLIT_OUT) {
                float v0 = acc[mb][nb][0], v1 = acc[mb][nb][1];
                float v2 = acc[mb][nb][2], v3 = acc[mb][nb][3];
                bf16 h0 = __float2bfloat16(v0), h1 = __float2bfloat16(v1);
                bf16 h2 = __float2bfloat16(v2), h3 = __float2bfloat16(v3);
                bf162 p;
                p.x = h0; p.y = h1; *(bf162*)(Chi + o0) = p;
                p.x = h2; p.y = h3; *(bf162*)(Chi + o1) = p;
                p.x = __float2bfloat16(v0 - __bfloat162float(h0));
                p.y = __float2bfloat16(v1 - __bfloat162float(h1));
                *(bf162*)(Clo + o0) = p;
                p.x = __float2bfloat16(v2 - __bfloat162float(h2));
                p.y = __float2bfloat16(v3 - __bfloat162float(h3));
                *(bf162*)(Clo + o1) = p;
            } else {
                *(float2*)(C + o0) = make_float2(acc[mb][nb][0], acc[mb][nb][1]);
                *(float2*)(C + o1) = make_float2(acc[mb][nb][2], acc[mb][nb][3]);
            }
        }
}

// ---------------- FUSED softmax + talking-heads mix + LN (v2) ---------------
#define SSTR 1032
__global__ __launch_bounds__(512) void softmax_mixln_kernel(
    const float* __restrict__ s, const float* __restrict__ Wt,
    const float* __restrict__ gamma, const float* __restrict__ beta,
    bf16* __restrict__ whi, bf16* __restrict__ wlo)
{
    extern __shared__ float sm[];            // [16][SSTR] probs
    __shared__ float wts[16][17];
    __shared__ float gm[16], bt[16];
    int t = threadIdx.x;
    if (t < 256) wts[t >> 4][t & 15] = Wt[t];
    if (t < 16) { gm[t] = gamma[t]; bt[t] = beta[t]; }

    long bi = blockIdx.x;                    // b*1024 + i
    int w = t >> 5, lane = t & 31;

    // register softmax: warp w handles head row h = w
    {
        const float4* rp4 = (const float4*)(s + bi * 16384 + (long)w * 1024);
        float4 v[8];
        float mx = -1e30f;
#pragma unroll
        for (int it = 0; it < 8; it++) {
            v[it] = rp4[lane + it * 32];
            mx = fmaxf(mx, fmaxf(fmaxf(v[it].x, v[it].y), fmaxf(v[it].z, v[it].w)));
        }
#pragma unroll
        for (int o = 16; o > 0; o >>= 1) mx = fmaxf(mx, __shfl_xor_sync(0xffffffffu, mx, o));
        float sum = 0.f;
#pragma unroll
        for (int it = 0; it < 8; it++) {
            v[it].x = __expf(0.125f * (v[it].x - mx));
            v[it].y = __expf(0.125f * (v[it].y - mx));
            v[it].z = __expf(0.125f * (v[it].z - mx));
            v[it].w = __expf(0.125f * (v[it].w - mx));
            sum += v[it].x + v[it].y + v[it].z + v[it].w;
        }
#pragma unroll
        for (int o = 16; o > 0; o >>= 1) sum += __shfl_xor_sync(0xffffffffu, sum, o);
        float inv = 1.f / sum;
#pragma unroll
        for (int it = 0; it < 8; it++) {
            v[it].x *= inv; v[it].y *= inv; v[it].z *= inv; v[it].w *= inv;
            *(float4*)&sm[w * SSTR + (lane + it * 32) * 4] = v[it];
        }
    }
    __syncthreads();

    // mix + LN: thread t handles j-pair (2t, 2t+1)
    long b = bi >> 10, i = bi & 1023;
    int j0 = t * 2;
    float sv0[16], sv1[16];
#pragma unroll
    for (int h = 0; h < 16; h++) {
        float2 v = *(const float2*)&sm[h * SSTR + j0];
        sv0[h] = v.x; sv1[h] = v.y;
    }
    float m0[16], m1[16], mu0 = 0.f, mu1 = 0.f;
#pragma unroll
    for (int g = 0; g < 16; g++) {
        float a = 0.f, b2 = 0.f;
#pragma unroll
        for (int h = 0; h < 16; h++) {
            a  = fmaf(sv0[h], wts[h][g], a);
            b2 = fmaf(sv1[h], wts[h][g], b2);
        }
        m0[g] = a; m1[g] = b2; mu0 += a; mu1 += b2;
    }
    mu0 *= (1.f / 16.f); mu1 *= (1.f / 16.f);
    float va0 = 0.f, va1 = 0.f;
#pragma unroll
    for (int g = 0; g < 16; g++) {
        float d0 = m0[g] - mu0, d1 = m1[g] - mu1;
        va0 = fmaf(d0, d0, va0); va1 = fmaf(d1, d1, va1);
    }
    float iv0 = rsqrtf(va0 * (1.f / 16.f) + LN_EPS);
    float iv1 = rsqrtf(va1 * (1.f / 16.f) + LN_EPS);
#pragma unroll
    for (int g = 0; g < 16; g++) {
        float w0 = (m0[g] - mu0) * iv0 * gm[g] + bt[g];
        float w1 = (m1[g] - mu1) * iv1 * gm[g] + bt[g];
        bf16 h0 = __float2bfloat16(w0), h1 = __float2bfloat16(w1);
        bf162 ph; ph.x = h0; ph.y = h1;
        bf162 pl;
        pl.x = __float2bfloat16(w0 - __bfloat162float(h0));
        pl.y = __float2bfloat16(w1 - __bfloat162float(h1));
        long ob = ((b * 16 + g) << 20) + (i << 10) + j0;
        *(bf162*)(whi + ob) = ph;
        *(bf162*)(wlo + ob) = pl;
    }
}

// ---------------- driver -----------------------------------------------------
extern "C" void kernel_launch(void* const* d_in, const int* in_sizes, int n_in,
                              void* d_out, int out_size)
{
    const float* x     = (const float*)d_in[0];
    const float* ctx   = (const float*)d_in[1];
    const float* Wq    = (const float*)d_in[2];
    const float* Wkv   = (const float*)d_in[3];
    const float* Wt    = (const float*)d_in[4];
    const float* gamma = (const float*)d_in[5];
    const float* beta  = (const float*)d_in[6];
    float* out = (float*)d_out;

    bf16 *xhi, *xlo, *chi, *clo, *wqThi, *wqTlo, *wkThi, *wkTlo;
    bf16 *qhi, *qlo, *kvhi, *kvlo, *vThi, *vTlo, *whi, *wlo;
    float *sp;
    cudaGetSymbolAddress((void**)&xhi, g_xhi);   cudaGetSymbolAddress((void**)&xlo, g_xlo);
    cudaGetSymbolAddress((void**)&chi, g_chi);   cudaGetSymbolAddress((void**)&clo, g_clo);
    cudaGetSymbolAddress((void**)&wqThi, g_wqThi); cudaGetSymbolAddress((void**)&wqTlo, g_wqTlo);
    cudaGetSymbolAddress((void**)&wkThi, g_wkThi); cudaGetSymbolAddress((void**)&wkTlo, g_wkTlo);
    cudaGetSymbolAddress((void**)&qhi, g_qhi);   cudaGetSymbolAddress((void**)&qlo, g_qlo);
    cudaGetSymbolAddress((void**)&kvhi, g_kvhi); cudaGetSymbolAddress((void**)&kvlo, g_kvlo);
    cudaGetSymbolAddress((void**)&vThi, g_vThi); cudaGetSymbolAddress((void**)&vTlo, g_vTlo);
    cudaGetSymbolAddress((void**)&whi, g_whi);   cudaGetSymbolAddress((void**)&wlo, g_wlo);
    cudaGetSymbolAddress((void**)&sp, g_s);

    // dynamic smem sizes for the GEMM shapes
    int smem_g1 = (2 * (128 * 40) + 2 * (128 * 40)) * 2 * 2;   // 81920 B
    int smem_g2 = (2 * (128 * 40) + 2 * (64 * 40)) * 2 * 2;    // 61440 B
    cudaFuncSetAttribute(gemm_bf16<128, 128, 64, 32, true>,
                         cudaFuncAttributeMaxDynamicSharedMemorySize, smem_g1);
    cudaFuncSetAttribute(gemm_bf16<128, 128, 64, 32, false>,
                         cudaFuncAttributeMaxDynamicSharedMemorySize, smem_g1);
    cudaFuncSetAttribute(gemm_bf16<128, 64, 32, 32, false>,
                         cudaFuncAttributeMaxDynamicSharedMemorySize, smem_g2);

    // 1. splits of inputs
    split_kernel<<<4096, 256>>>(x, xhi, xlo, 4194304);
    split_kernel<<<4096, 256>>>(ctx, chi, clo, 4194304);
    tsplit_kernel<<<dim3(32, 32, 1), 256>>>(Wq, 0, 1024, wqThi, wqTlo, 0, 1024);
    tsplit_kernel<<<dim3(64, 32, 1), 256>>>(Wkv, 0, 2048, wkThi, wkTlo, 0, 1024);

    // 2. projections with split epilogue: q, kv directly as bf16 hi/lo
    gemm_bf16<128, 128, 64, 32, true><<<dim3(8, 32, 1), 256, smem_g1>>>(
        xhi, xlo, wqThi, wqTlo, nullptr, qhi, qlo, 1024, 1024, 1024, 1024,
        1, 0, 0, 0, 0, 0, 0);
    gemm_bf16<128, 128, 64, 32, true><<<dim3(16, 32, 1), 256, smem_g1>>>(
        chi, clo, wkThi, wkTlo, nullptr, kvhi, kvlo, 1024, 1024, 1024, 2048,
        1, 0, 0, 0, 0, 0, 0);

    // 3. v^T per batch from split kv (lossless bf16 transpose)
    tbf16_kernel<<<dim3(32, 32, 4), 256>>>(
        kvhi + 1024, kvlo + 1024, 2097152, 2048, vThi, vTlo, 1048576, 1024);

    // 4. raw scores per (b,h): S = Q_h K_h^T -> g_s [b][i][h][j]
    gemm_bf16<128, 128, 64, 32, false><<<dim3(8, 8, 64), 256, smem_g1>>>(
        qhi, qlo, kvhi, kvlo, sp, nullptr, nullptr, 64, 1024, 2048, 16384,
        16, 1048576, 64, 2097152, 64, 16777216, 1024);

    // 5+6 fused: softmax + talking-heads mix + LN (512 thr, 1 sync)
    int smem_f = 16 * SSTR * 4;
    cudaFuncSetAttribute(softmax_mixln_kernel,
                         cudaFuncAttributeMaxDynamicSharedMemorySize, smem_f);
    softmax_mixln_kernel<<<4096, 512, smem_f>>>(sp, Wt, gamma, beta, whi, wlo);

    // 7. AV per (b,g): out[i][g*64+d] = sum_j w[i][j] v[j][d]
    gemm_bf16<128, 64, 32, 32, false><<<dim3(1, 8, 64), 256, smem_g2>>>(
        whi, wlo, vThi, vTlo, out, nullptr, nullptr, 1024, 1024, 1024, 1024,
        16, 16777216, 1048576, 1048576, 65536, 1048576, 64);
}